// round 2
// baseline (speedup 1.0000x reference)
#include <cuda_runtime.h>
#include <cuda_bf16.h>

// Problem constants
#define NB 4
#define SS 4096
#define DD 1024
#define AA 1024
#define NTOK (NB * SS)   // 16384

// Scratch (device globals: allocation-free rule)
__device__ float g_Q[(size_t)NB * SS * AA];            // 64 MB
__device__ float g_K[(size_t)NB * SS * AA];            // 64 MB
__device__ float g_V[(size_t)NB * SS * AA];            // 64 MB
__device__ float g_P[(size_t)NB * SS * SS];            // 256 MB (scores / attn)
__device__ float g_C[(size_t)NB * SS * AA];            // 64 MB (context)

// ---------------------------------------------------------------------------
// SGEMM: C = alpha * A * op(B) + bias
//   A: [M, K] row-major
//   TRANS_B = true : B is [N, K] row-major (C = A * B^T)   -- torch Linear / Q*K^T
//   TRANS_B = false: B is [K, N] row-major (C = A * B)     -- attn * V
// Tiling: BM=BN=64, BK=16, 256 threads, each thread computes 4x4.
// All dims assumed multiples of 64 (M,N) and 16 (K) -- true for this problem.
// ---------------------------------------------------------------------------
template <bool TRANS_B>
__global__ __launch_bounds__(256) void sgemm_kernel(
    const float* __restrict__ Ag, const float* __restrict__ Bg,
    const float* __restrict__ bias, float* __restrict__ Cg,
    int M, int N, int K, float alpha,
    long strideA, long strideB, long strideC)
{
    const int bz = blockIdx.z;
    const float* Ap = Ag + (long)bz * strideA;
    const float* Bp = Bg + (long)bz * strideB;
    float* Cp = Cg + (long)bz * strideC;

    __shared__ float As[16][68];   // [k][m], padded
    __shared__ float Bs[16][68];   // [k][n], padded

    const int tid = threadIdx.x;
    const int m0 = blockIdx.y * 64;
    const int n0 = blockIdx.x * 64;

    const int ty = tid >> 4;        // 0..15 (row group)
    const int tx = tid & 15;        // 0..15 (col group)

    // Loader indices (transposing load path): 64 rows x 16 cols per tile
    const int lr = tid >> 2;        // 0..63 tile row
    const int lc = (tid & 3) * 4;   // 0,4,8,12 k-col

    float acc[4][4] = {};

    for (int k0 = 0; k0 < K; k0 += 16) {
        // Load A tile -> As[k][m] (transpose in smem)
        {
            float4 v = *(const float4*)(Ap + (long)(m0 + lr) * K + (k0 + lc));
            As[lc + 0][lr] = v.x;
            As[lc + 1][lr] = v.y;
            As[lc + 2][lr] = v.z;
            As[lc + 3][lr] = v.w;
        }
        if (TRANS_B) {
            // B row-major [N, K]: row (n0+lr), cols k0+lc..  -> Bs[k][n]
            float4 v = *(const float4*)(Bp + (long)(n0 + lr) * K + (k0 + lc));
            Bs[lc + 0][lr] = v.x;
            Bs[lc + 1][lr] = v.y;
            Bs[lc + 2][lr] = v.z;
            Bs[lc + 3][lr] = v.w;
        } else {
            // B row-major [K, N]: row (k0+br), cols n0+bc.. -> Bs[k][n] direct
            const int br = tid >> 4;          // 0..15 k row
            const int bc = (tid & 15) * 4;    // 0..60 n col
            float4 v = *(const float4*)(Bp + (long)(k0 + br) * N + (n0 + bc));
            *(float4*)&Bs[br][bc] = v;
        }
        __syncthreads();

        #pragma unroll
        for (int k = 0; k < 16; ++k) {
            float4 a = *(const float4*)&As[k][ty * 4];
            float4 b = *(const float4*)&Bs[k][tx * 4];
            float av[4] = {a.x, a.y, a.z, a.w};
            float bv[4] = {b.x, b.y, b.z, b.w};
            #pragma unroll
            for (int i = 0; i < 4; ++i)
                #pragma unroll
                for (int j = 0; j < 4; ++j)
                    acc[i][j] = fmaf(av[i], bv[j], acc[i][j]);
        }
        __syncthreads();
    }

    #pragma unroll
    for (int i = 0; i < 4; ++i) {
        const int m = m0 + ty * 4 + i;
        #pragma unroll
        for (int j = 0; j < 4; ++j) {
            const int n = n0 + tx * 4 + j;
            float v = acc[i][j] * alpha;
            if (bias) v += bias[n];
            Cp[(long)m * N + n] = v;
        }
    }
}

// ---------------------------------------------------------------------------
// Row softmax in-place: one block (256 threads) per row of length n.
// ---------------------------------------------------------------------------
__global__ __launch_bounds__(256) void softmax_rows_kernel(float* __restrict__ P, int n)
{
    float* p = P + (long)blockIdx.x * n;
    const int tid = threadIdx.x;
    __shared__ float red[256];

    float mx = -1e30f;
    for (int i = tid; i < n; i += 256) mx = fmaxf(mx, p[i]);
    red[tid] = mx;
    __syncthreads();
    #pragma unroll
    for (int s = 128; s > 0; s >>= 1) {
        if (tid < s) red[tid] = fmaxf(red[tid], red[tid + s]);
        __syncthreads();
    }
    mx = red[0];
    __syncthreads();

    float sum = 0.0f;
    for (int i = tid; i < n; i += 256) {
        float e = __expf(p[i] - mx);
        p[i] = e;
        sum += e;
    }
    red[tid] = sum;
    __syncthreads();
    #pragma unroll
    for (int s = 128; s > 0; s >>= 1) {
        if (tid < s) red[tid] += red[tid + s];
        __syncthreads();
    }
    const float inv = 1.0f / red[0];
    for (int i = tid; i < n; i += 256) p[i] *= inv;
}

// ---------------------------------------------------------------------------
// Launch
// ---------------------------------------------------------------------------
extern "C" void kernel_launch(void* const* d_in, const int* in_sizes, int n_in,
                              void* d_out, int out_size)
{
    const float* x  = (const float*)d_in[0];
    const float* Wq = (const float*)d_in[1];
    const float* bq = (const float*)d_in[2];
    const float* Wk = (const float*)d_in[3];
    const float* bk = (const float*)d_in[4];
    const float* Wv = (const float*)d_in[5];
    const float* bv = (const float*)d_in[6];
    const float* Wo = (const float*)d_in[7];
    const float* bo = (const float*)d_in[8];
    float* out = (float*)d_out;

    float *Q, *K, *V, *P, *C;
    cudaGetSymbolAddress((void**)&Q, g_Q);
    cudaGetSymbolAddress((void**)&K, g_K);
    cudaGetSymbolAddress((void**)&V, g_V);
    cudaGetSymbolAddress((void**)&P, g_P);
    cudaGetSymbolAddress((void**)&C, g_C);

    const float scale = 0.03125f;  // 1/sqrt(1024)
    dim3 blk(256);

    // Projections: [NTOK, DD] x [AA, DD]^T -> [NTOK, AA]
    dim3 gproj(AA / 64, NTOK / 64, 1);
    sgemm_kernel<true><<<gproj, blk>>>(x, Wq, bq, Q, NTOK, AA, DD, 1.0f, 0, 0, 0);
    sgemm_kernel<true><<<gproj, blk>>>(x, Wk, bk, K, NTOK, AA, DD, 1.0f, 0, 0, 0);
    sgemm_kernel<true><<<gproj, blk>>>(x, Wv, bv, V, NTOK, AA, DD, 1.0f, 0, 0, 0);

    // Scores: per-batch [SS, AA] x [SS, AA]^T * scale -> [SS, SS]
    dim3 gsc(SS / 64, SS / 64, NB);
    sgemm_kernel<true><<<gsc, blk>>>(Q, K, nullptr, P, SS, SS, AA, scale,
                                     (long)SS * AA, (long)SS * AA, (long)SS * SS);

    // Softmax over last dim
    softmax_rows_kernel<<<NB * SS, 256>>>(P, SS);

    // Context: per-batch [SS, SS] x [SS, AA] -> [SS, AA]
    dim3 gctx(AA / 64, SS / 64, NB);
    sgemm_kernel<false><<<gctx, blk>>>(P, V, nullptr, C, SS, AA, SS, 1.0f,
                                       (long)SS * SS, (long)SS * AA, (long)SS * AA);

    // Output projection: [NTOK, AA] x [DD, AA]^T + bo -> [NTOK, DD]
    sgemm_kernel<true><<<gproj, blk>>>(C, Wo, bo, out, NTOK, DD, AA, 1.0f, 0, 0, 0);
}